// round 17
// baseline (speedup 1.0000x reference)
#include <cuda_runtime.h>
#include <cuda_bf16.h>
#include <stdint.h>
#include <math.h>

#define NHEADS 16
#define INDIM  1024
#define DHEAD  64
#define BATCH  2
#define SEQ    2048
#define NTOK   (BATCH*SEQ)
#define BH     (BATCH*NHEADS)

// fp32 V scratch (needed for the transpose pass), layout [B*H][S][DHEAD]
__device__ float g_v[(size_t)BH*SEQ*DHEAD];

// Split-precision inputs for bf16 tensor-core MMA (raw u16 payloads).
__device__ unsigned short g_xhi[(size_t)NTOK*INDIM];
__device__ unsigned short g_xlo[(size_t)NTOK*INDIM];
__device__ unsigned short g_xh16[(size_t)NTOK*INDIM];     // single fp16 x (v-proj)
__device__ unsigned short g_wthi[(size_t)NHEADS*3*DHEAD*INDIM];
__device__ unsigned short g_wtlo[(size_t)NHEADS*3*DHEAD*INDIM];
__device__ unsigned short g_wvh16[(size_t)NHEADS*DHEAD*INDIM];  // single fp16 Wv^T

// Attention operands: q fp16 hi/lo split, k single fp16 ([bh][s][d]);
// v transposed single fp16 ([bh][d][s]).
__device__ unsigned short g_qhi[(size_t)BH*SEQ*DHEAD];
__device__ unsigned short g_qlo[(size_t)BH*SEQ*DHEAD];
__device__ unsigned short g_khi[(size_t)BH*SEQ*DHEAD];
__device__ unsigned short g_vthi[(size_t)BH*DHEAD*SEQ];

__device__ __forceinline__ uint32_t smem_u32(const void* p) {
    uint32_t a;
    asm("{ .reg .u64 t; cvta.to.shared.u64 t, %1; cvt.u32.u64 %0, t; }"
        : "=r"(a) : "l"(p));
    return a;
}

__device__ __forceinline__ unsigned short f2bf_hi(float f) {
    __nv_bfloat16 h = __float2bfloat16(f);
    __nv_bfloat16_raw r = *(__nv_bfloat16_raw*)&h;
    return r.x;
}
__device__ __forceinline__ float bf2f(unsigned short u) {
    return __uint_as_float((uint32_t)u << 16);
}
// fp16 conversions via bare PTX (no cuda_fp16.h dependency)
__device__ __forceinline__ unsigned short f2h_raw(float f) {
    unsigned short r;
    asm("cvt.rn.f16.f32 %0, %1;" : "=h"(r) : "f"(f));
    return r;
}
__device__ __forceinline__ float h2f(unsigned short u) {
    float f;
    asm("cvt.f32.f16 %0, %1;" : "=f"(f) : "h"(u));
    return f;
}
// pack two floats to fp16x2 (lo = x, hi = y) in one cvt
__device__ __forceinline__ uint32_t pack_h2(float x, float y) {
    uint32_t r;
    asm("cvt.rn.f16x2.f32 %0, %1, %2;" : "=r"(r) : "f"(y), "f"(x));
    return r;
}

// split (x,y) -> fp16 hi-pair and fp16 residual-pair (lower 16 bits = x)
__device__ __forceinline__ void split_pack2_h(float x, float y,
                                              uint32_t& hi, uint32_t& lo) {
    unsigned short hx = f2h_raw(x), hy = f2h_raw(y);
    float rx = x - h2f(hx);
    float ry = y - h2f(hy);
    hi = (uint32_t)hx | ((uint32_t)hy << 16);
    lo = (uint32_t)f2h_raw(rx) | ((uint32_t)f2h_raw(ry) << 16);
}

// bf16 mma: D(f32) = A(bf16,row) x B(bf16,col) + C, m16n8k16.
__device__ __forceinline__ void mma_bf16(float* c, const uint32_t* a,
                                         const uint32_t* b) {
    float d0, d1, d2, d3;
    asm volatile(
        "mma.sync.aligned.m16n8k16.row.col.f32.bf16.bf16.f32 "
        "{%0,%1,%2,%3}, {%4,%5,%6,%7}, {%8,%9}, {%10,%11,%12,%13};"
        : "=f"(d0), "=f"(d1), "=f"(d2), "=f"(d3)
        : "r"(a[0]), "r"(a[1]), "r"(a[2]), "r"(a[3]),
          "r"(b[0]), "r"(b[1]),
          "f"(c[0]), "f"(c[1]), "f"(c[2]), "f"(c[3]));
    c[0] = d0; c[1] = d1; c[2] = d2; c[3] = d3;
}

// fp16 mma: D(f32) = A(f16,row) x B(f16,col) + C, m16n8k16.
__device__ __forceinline__ void mma_f16(float* c, const uint32_t* a,
                                        const uint32_t* b) {
    float d0, d1, d2, d3;
    asm volatile(
        "mma.sync.aligned.m16n8k16.row.col.f32.f16.f16.f32 "
        "{%0,%1,%2,%3}, {%4,%5,%6,%7}, {%8,%9}, {%10,%11,%12,%13};"
        : "=f"(d0), "=f"(d1), "=f"(d2), "=f"(d3)
        : "r"(a[0]), "r"(a[1]), "r"(a[2]), "r"(a[3]),
          "r"(b[0]), "r"(b[1]),
          "f"(c[0]), "f"(c[1]), "f"(c[2]), "f"(c[3]));
    c[0] = d0; c[1] = d1; c[2] = d2; c[3] = d3;
}

#define LDMATRIX_X4(r0, r1, r2, r3, addr)                                      \
    asm volatile("ldmatrix.sync.aligned.m8n8.x4.shared.b16 {%0,%1,%2,%3}, [%4];" \
                 : "=r"(r0), "=r"(r1), "=r"(r2), "=r"(r3) : "r"(addr))

#define CP_ASYNC16(smem_addr, gptr)                                            \
    asm volatile("cp.async.cg.shared.global [%0], [%1], 16;"                   \
                 :: "r"(smem_addr), "l"(gptr) : "memory")
#define CP_COMMIT()  asm volatile("cp.async.commit_group;" ::: "memory")
#define CP_WAIT0()   asm volatile("cp.async.wait_group 0;" ::: "memory")

// ---------------------------------------------------------------------------
// convert_x: x fp32 -> bf16 hi/lo split + single fp16.
// ---------------------------------------------------------------------------
__global__ __launch_bounds__(256)
void convert_x(const float* __restrict__ x)
{
    int i = blockIdx.x * 256 + threadIdx.x;
    float4 v = ((const float4*)x)[i];
    float f[4] = {v.x, v.y, v.z, v.w};
    ushort4 hh, ll, h16;
    unsigned short* hp = (unsigned short*)&hh;
    unsigned short* lp = (unsigned short*)&ll;
    unsigned short* gp = (unsigned short*)&h16;
#pragma unroll
    for (int j = 0; j < 4; j++) {
        unsigned short hu = f2bf_hi(f[j]);
        hp[j] = hu; lp[j] = f2bf_hi(f[j] - bf2f(hu));
        gp[j] = f2h_raw(f[j]);
    }
    ((ushort4*)g_xhi)[i] = hh;
    ((ushort4*)g_xlo)[i] = ll;
    ((ushort4*)g_xh16)[i] = h16;
}

// ---------------------------------------------------------------------------
// convert_w: W[h][k][n] fp32 -> transposed [n][k]; q/k as bf16 hi/lo,
// v as single fp16.
// ---------------------------------------------------------------------------
__global__ __launch_bounds__(256)
void convert_w(const float* __restrict__ Wq, const float* __restrict__ Wk,
               const float* __restrict__ Wv)
{
    __shared__ float tile[64][65];
    const int k0 = blockIdx.x * 64;
    const int hp = blockIdx.y;
    const int h  = hp / 3, p = hp % 3;
    const float* W = ((p == 0) ? Wq : (p == 1) ? Wk : Wv) + (size_t)h * INDIM * DHEAD;
    const int tid = threadIdx.x;

#pragma unroll
    for (int it = 0; it < 16; it++) {
        int idx = tid + it * 256;
        int kk = idx >> 6, n = idx & 63;
        tile[kk][n] = W[(size_t)(k0 + kk) * DHEAD + n];
    }
    __syncthreads();
#pragma unroll
    for (int it = 0; it < 16; it++) {
        int idx = tid + it * 256;
        int n = idx >> 6, kk = idx & 63;
        float v = tile[kk][n];
        if (p < 2) {
            unsigned short hu = f2bf_hi(v);
            size_t o = (size_t)hp * DHEAD * INDIM + (size_t)n * INDIM + k0 + kk;
            g_wthi[o] = hu; g_wtlo[o] = f2bf_hi(v - bf2f(hu));
        } else {
            size_t o = ((size_t)h * DHEAD + n) * INDIM + k0 + kk;
            g_wvh16[o] = f2h_raw(v);
        }
    }
}

// ---------------------------------------------------------------------------
// proj_mma: q/k projections, bf16 3-term (validated). grid z in {0,1}.
//   q -> fp16 hi/lo split, k -> single fp16.
// ---------------------------------------------------------------------------
#define AHI_OFF 0
#define ALO_OFF (128*72)
#define BHI_OFF (2*128*72)
#define BLO_OFF (2*128*72 + 64*72)
#define PROJ_SMEM_ELEMS (2*128*72 + 2*64*72)

__global__ __launch_bounds__(128)
void proj_mma(const float* __restrict__ bq, const float* __restrict__ bk)
{
    extern __shared__ char smem_raw[];
    unsigned short* sb = (unsigned short*)smem_raw;
    const uint32_t sbase = smem_u32(sb);

    const int tid  = threadIdx.x;
    const int wid  = tid >> 5;
    const int lane = tid & 31;
    const int mbase = blockIdx.x * 128;
    const int h     = blockIdx.y;
    const int p     = blockIdx.z;

    const unsigned short* Whi = g_wthi + (size_t)(h * 3 + p) * DHEAD * INDIM;
    const unsigned short* Wlo = g_wtlo + (size_t)(h * 3 + p) * DHEAD * INDIM;

    float acc[2][8][4];
#pragma unroll
    for (int mt = 0; mt < 2; mt++)
#pragma unroll
        for (int nt = 0; nt < 8; nt++)
#pragma unroll
            for (int e = 0; e < 4; e++) acc[mt][nt][e] = 0.f;

    const int mi   = lane >> 3;
    const int l8   = lane & 7;
    const int a_rofs = l8 + (mi & 1) * 8;
    const int a_kofs = (mi >> 1) * 8;
    const int b_nofs = l8 + (mi >> 1) * 8;
    const int b_kofs = (mi & 1) * 8;

    for (int c = 0; c < 16; c++) {
        __syncthreads();
#pragma unroll
        for (int it = 0; it < 8; it++) {
            int idx = tid + it * 128;
            int r = idx >> 3, sg = idx & 7;
            *(uint4*)(sb + AHI_OFF + r * 72 + sg * 8) =
                *(const uint4*)(g_xhi + (size_t)(mbase + r) * INDIM + c * 64 + sg * 8);
            *(uint4*)(sb + ALO_OFF + r * 72 + sg * 8) =
                *(const uint4*)(g_xlo + (size_t)(mbase + r) * INDIM + c * 64 + sg * 8);
        }
#pragma unroll
        for (int it = 0; it < 4; it++) {
            int idx = tid + it * 128;
            int n = idx >> 3, sg = idx & 7;
            *(uint4*)(sb + BHI_OFF + n * 72 + sg * 8) =
                *(const uint4*)(Whi + (size_t)n * INDIM + c * 64 + sg * 8);
            *(uint4*)(sb + BLO_OFF + n * 72 + sg * 8) =
                *(const uint4*)(Wlo + (size_t)n * INDIM + c * 64 + sg * 8);
        }
        __syncthreads();

#pragma unroll
        for (int ks = 0; ks < 4; ks++) {
            const int k0 = ks * 16;
            uint32_t bhi[8][2], blo[8][2];
#pragma unroll
            for (int np = 0; np < 4; np++) {
                int n = np * 16 + b_nofs;
                uint32_t ah = sbase + (uint32_t)(BHI_OFF + n * 72 + k0 + b_kofs) * 2;
                uint32_t al = sbase + (uint32_t)(BLO_OFF + n * 72 + k0 + b_kofs) * 2;
                LDMATRIX_X4(bhi[np*2][0], bhi[np*2][1], bhi[np*2+1][0], bhi[np*2+1][1], ah);
                LDMATRIX_X4(blo[np*2][0], blo[np*2][1], blo[np*2+1][0], blo[np*2+1][1], al);
            }
#pragma unroll
            for (int mt = 0; mt < 2; mt++) {
                int r = wid * 32 + mt * 16 + a_rofs;
                uint32_t ahad = sbase + (uint32_t)(AHI_OFF + r * 72 + k0 + a_kofs) * 2;
                uint32_t alad = sbase + (uint32_t)(ALO_OFF + r * 72 + k0 + a_kofs) * 2;
                uint32_t ah[4], al[4];
                LDMATRIX_X4(ah[0], ah[1], ah[2], ah[3], ahad);
                LDMATRIX_X4(al[0], al[1], al[2], al[3], alad);
#pragma unroll
                for (int nt = 0; nt < 8; nt++) {
                    mma_bf16(acc[mt][nt], ah, bhi[nt]);
                    mma_bf16(acc[mt][nt], ah, blo[nt]);
                    mma_bf16(acc[mt][nt], al, bhi[nt]);
                }
            }
        }
    }

    const float* bias = (p == 0 ? bq : bk) + h * DHEAD;
    const int quad = lane >> 2, pr = lane & 3;

#pragma unroll
    for (int mt = 0; mt < 2; mt++) {
#pragma unroll
        for (int half = 0; half < 2; half++) {
            int tok = mbase + wid * 32 + mt * 16 + quad + half * 8;
            int b = tok >> 11, s = tok & 2047;
            size_t base = ((size_t)(b * NHEADS + h) * SEQ + s) * DHEAD;
            if (p == 0) {
#pragma unroll
                for (int nt = 0; nt < 8; nt++) {
                    int col = nt * 8 + pr * 2;
                    float2 bb = *(const float2*)(bias + col);
                    uint32_t ph, pl;
                    split_pack2_h(acc[mt][nt][half*2 + 0] + bb.x,
                                  acc[mt][nt][half*2 + 1] + bb.y, ph, pl);
                    *(uint32_t*)(g_qhi + base + col) = ph;
                    *(uint32_t*)(g_qlo + base + col) = pl;
                }
            } else {
#pragma unroll
                for (int nt = 0; nt < 8; nt++) {
                    int col = nt * 8 + pr * 2;
                    float2 bb = *(const float2*)(bias + col);
                    *(uint32_t*)(g_khi + base + col) =
                        pack_h2(acc[mt][nt][half*2 + 0] + bb.x,
                                acc[mt][nt][half*2 + 1] + bb.y);
                }
            }
        }
    }
}

// ---------------------------------------------------------------------------
// proj_v: v projection, single-term fp16 (post-softmax error channel).
// Grid (NTOK/128, NHEADS), 128 threads. Writes fp32 g_v with bias.
// ---------------------------------------------------------------------------
#define PV_XH 0
#define PV_WH (128*72)
#define PROJV_SMEM ((128*72 + 64*72) * 2)

__global__ __launch_bounds__(128)
void proj_v(const float* __restrict__ bv)
{
    extern __shared__ char smem_raw[];
    unsigned short* sb = (unsigned short*)smem_raw;
    const uint32_t sbase = smem_u32(sb);

    const int tid  = threadIdx.x;
    const int wid  = tid >> 5;
    const int lane = tid & 31;
    const int mbase = blockIdx.x * 128;
    const int h     = blockIdx.y;

    const unsigned short* Wv = g_wvh16 + (size_t)h * DHEAD * INDIM;

    float acc[2][8][4];
#pragma unroll
    for (int mt = 0; mt < 2; mt++)
#pragma unroll
        for (int nt = 0; nt < 8; nt++)
#pragma unroll
            for (int e = 0; e < 4; e++) acc[mt][nt][e] = 0.f;

    const int mi   = lane >> 3;
    const int l8   = lane & 7;
    const int a_rofs = l8 + (mi & 1) * 8;
    const int a_kofs = (mi >> 1) * 8;
    const int b_nofs = l8 + (mi >> 1) * 8;
    const int b_kofs = (mi & 1) * 8;

    for (int c = 0; c < 16; c++) {
        __syncthreads();
#pragma unroll
        for (int it = 0; it < 8; it++) {
            int idx = tid + it * 128;
            int r = idx >> 3, sg = idx & 7;
            *(uint4*)(sb + PV_XH + r * 72 + sg * 8) =
                *(const uint4*)(g_xh16 + (size_t)(mbase + r) * INDIM + c * 64 + sg * 8);
        }
#pragma unroll
        for (int it = 0; it < 4; it++) {
            int idx = tid + it * 128;
            int n = idx >> 3, sg = idx & 7;
            *(uint4*)(sb + PV_WH + n * 72 + sg * 8) =
                *(const uint4*)(Wv + (size_t)n * INDIM + c * 64 + sg * 8);
        }
        __syncthreads();

#pragma unroll
        for (int ks = 0; ks < 4; ks++) {
            const int k0 = ks * 16;
            uint32_t bh[8][2];
#pragma unroll
            for (int np = 0; np < 4; np++) {
                int n = np * 16 + b_nofs;
                uint32_t ad = sbase + (uint32_t)(PV_WH + n * 72 + k0 + b_kofs) * 2;
                LDMATRIX_X4(bh[np*2][0], bh[np*2][1], bh[np*2+1][0], bh[np*2+1][1], ad);
            }
#pragma unroll
            for (int mt = 0; mt < 2; mt++) {
                int r = wid * 32 + mt * 16 + a_rofs;
                uint32_t aad = sbase + (uint32_t)(PV_XH + r * 72 + k0 + a_kofs) * 2;
                uint32_t a[4];
                LDMATRIX_X4(a[0], a[1], a[2], a[3], aad);
#pragma unroll
                for (int nt = 0; nt < 8; nt++)
                    mma_f16(acc[mt][nt], a, bh[nt]);
            }
        }
    }

    const float* bias = bv + h * DHEAD;
    const int quad = lane >> 2, pr = lane & 3;

#pragma unroll
    for (int mt = 0; mt < 2; mt++) {
#pragma unroll
        for (int half = 0; half < 2; half++) {
            int tok = mbase + wid * 32 + mt * 16 + quad + half * 8;
            int b = tok >> 11, s = tok & 2047;
            float* dst = g_v + ((size_t)(b * NHEADS + h) * SEQ + s) * DHEAD;
#pragma unroll
            for (int nt = 0; nt < 8; nt++) {
                int col = nt * 8 + pr * 2;
                float2 bb = *(const float2*)(bias + col);
                float2 v;
                v.x = acc[mt][nt][half*2 + 0] + bb.x;
                v.y = acc[mt][nt][half*2 + 1] + bb.y;
                *(float2*)(dst + col) = v;
            }
        }
    }
}

// ---------------------------------------------------------------------------
// convert_vt: v fp32 [bh][s][d] -> single FP16, [bh][d][s].
// ---------------------------------------------------------------------------
__global__ __launch_bounds__(256)
void convert_vt()
{
    __shared__ float tile[64][65];
    const int s0 = blockIdx.x * 64;
    const int bh = blockIdx.y;
    const int tid = threadIdx.x;
    const float* V = g_v + (size_t)bh * SEQ * DHEAD;

#pragma unroll
    for (int it = 0; it < 16; it++) {
        int idx = tid + it * 256;
        int r = idx >> 6, d = idx & 63;
        tile[r][d] = V[(size_t)(s0 + r) * DHEAD + d];
    }
    __syncthreads();
#pragma unroll
    for (int it = 0; it < 16; it++) {
        int idx = tid + it * 256;
        int d = idx >> 6, cc = idx & 63;
        size_t o = (size_t)bh * DHEAD * SEQ + (size_t)d * SEQ + s0 + cc;
        g_vthi[o] = f2h_raw(tile[cc][d]);
    }
}

// ---------------------------------------------------------------------------
// attn_mma: QK^T = fp16, q-split x single-k (2 MMAs); PV = fp16, single-P x
// single-V (1 MMA). cp.async 2-stage ring. (validated round 16)
// ---------------------------------------------------------------------------
#define TQ_HI 0
#define TQ_LO 4608            // 64*72
#define BUF0  9216            // 2*64*72
#define BUFSZ 9216            // 2*64*72 (K + V)
#define ATTN_SMEM_BYTES ((2*4608 + 2*BUFSZ) * 2)   // 55296 B -> 4 CTAs/SM

__device__ __forceinline__ void attn_load_chunk(
    uint32_t sbase, int tid, int kb, int bufbase,
    const unsigned short* Khi, const unsigned short* Vthi)
{
#pragma unroll
    for (int it = 0; it < 4; it++) {            // K (single fp16): 512 slots
        int idx = tid + it * 128;
        int r = idx >> 3, sg = idx & 7;
        const unsigned short* src = Khi + (size_t)(kb + r) * DHEAD + sg * 8;
        uint32_t dst = sbase + (uint32_t)(bufbase + r * 72 + sg * 8) * 2;
        CP_ASYNC16(dst, src);
    }
#pragma unroll
    for (int it = 0; it < 4; it++) {            // Vt (single fp16): 512 slots
        int idx = tid + it * 128;
        int r = idx >> 3, sg = idx & 7;         // r = dv row
        const unsigned short* src = Vthi + (size_t)r * SEQ + kb + sg * 8;
        uint32_t dst = sbase + (uint32_t)(bufbase + 4608 + r * 72 + sg * 8) * 2;
        CP_ASYNC16(dst, src);
    }
    CP_COMMIT();
}

__global__ __launch_bounds__(128)
void attn_mma(float* __restrict__ out)
{
    extern __shared__ char smem_raw[];
    unsigned short* sb = (unsigned short*)smem_raw;
    const uint32_t sbase = smem_u32(sb);

    const int tid  = threadIdx.x;
    const int wq   = tid >> 5;
    const int lane = tid & 31;
    const int quad = lane >> 2, pr = lane & 3;
    const int mi   = lane >> 3, l8 = lane & 7;
    const int a_rofs = l8 + (mi & 1) * 8;
    const int a_kofs = (mi >> 1) * 8;
    const int b_nofs = l8 + (mi >> 1) * 8;
    const int b_kofs = (mi & 1) * 8;

    const int qbase = blockIdx.x * 64;
    const int bh    = blockIdx.y;

    const unsigned short* Qhi = g_qhi + (size_t)bh * SEQ * DHEAD;
    const unsigned short* Qlo = g_qlo + (size_t)bh * SEQ * DHEAD;
    const unsigned short* Khi = g_khi + (size_t)bh * SEQ * DHEAD;
    const unsigned short* Vthi = g_vthi + (size_t)bh * DHEAD * SEQ;

    // prologue: Q tile (hi/lo fp16) + chunk 0
#pragma unroll
    for (int it = 0; it < 8; it++) {
        int idx  = tid + it * 128;
        int half = idx >> 9;
        int rem  = idx & 511;
        int r    = rem >> 3, sg = rem & 7;
        const unsigned short* src =
            (half ? Qlo : Qhi) + (size_t)(qbase + r) * DHEAD + sg * 8;
        uint32_t dst = sbase + (uint32_t)((half ? TQ_LO : TQ_HI) + r * 72 + sg * 8) * 2;
        CP_ASYNC16(dst, src);
    }
    attn_load_chunk(sbase, tid, 0, BUF0, Khi, Vthi);

    float oacc[8][4];
    float mrow[2] = {-1e30f, -1e30f}, lrow[2] = {0.f, 0.f};
#pragma unroll
    for (int nt = 0; nt < 8; nt++)
#pragma unroll
        for (int e = 0; e < 4; e++) oacc[nt][e] = 0.f;

    const int NCHUNK = SEQ / 64;
    for (int i = 0; i < NCHUNK; i++) {
        CP_WAIT0();
        __syncthreads();
        if (i + 1 < NCHUNK)
            attn_load_chunk(sbase, tid, (i + 1) * 64,
                            BUF0 + ((i + 1) & 1) * BUFSZ, Khi, Vthi);

        const int Bb = BUF0 + (i & 1) * BUFSZ;
        const int TK = Bb;
        const int TV = Bb + 4608;

        // ---- QK^T (fp16): q hi/lo split x single k, 2 MMAs per n-tile ----
        float c[8][4];
#pragma unroll
        for (int nt = 0; nt < 8; nt++)
#pragma unroll
            for (int e = 0; e < 4; e++) c[nt][e] = 0.f;

#pragma unroll
        for (int ks = 0; ks < 4; ks++) {
            const int k0 = ks * 16;
            uint32_t qh[4], ql[4];
            {
                int r = wq * 16 + a_rofs;
                LDMATRIX_X4(qh[0], qh[1], qh[2], qh[3],
                            sbase + (uint32_t)(TQ_HI + r * 72 + k0 + a_kofs) * 2);
                LDMATRIX_X4(ql[0], ql[1], ql[2], ql[3],
                            sbase + (uint32_t)(TQ_LO + r * 72 + k0 + a_kofs) * 2);
            }
#pragma unroll
            for (int np = 0; np < 4; np++) {
                int n = np * 16 + b_nofs;
                uint32_t kh[4];
                LDMATRIX_X4(kh[0], kh[1], kh[2], kh[3],
                            sbase + (uint32_t)(TK + n * 72 + k0 + b_kofs) * 2);
                uint32_t b0h[2] = {kh[0], kh[1]}, b1h[2] = {kh[2], kh[3]};
                mma_f16(c[np*2],   qh, b0h);
                mma_f16(c[np*2],   ql, b0h);
                mma_f16(c[np*2+1], qh, b1h);
                mma_f16(c[np*2+1], ql, b1h);
            }
        }

        // ---- online softmax (rows quad / quad+8; 4 lanes per row) ----
#pragma unroll
        for (int r = 0; r < 2; r++) {
            const int e = r * 2;
            float mx = c[0][e];
#pragma unroll
            for (int nt = 0; nt < 8; nt++)
                mx = fmaxf(mx, fmaxf(c[nt][e], c[nt][e+1]));
            mx = fmaxf(mx, __shfl_xor_sync(0xffffffffu, mx, 1));
            mx = fmaxf(mx, __shfl_xor_sync(0xffffffffu, mx, 2));
            float mnew  = fmaxf(mrow[r], mx);
            float alpha = __expf(mrow[r] - mnew);
            float ps = 0.f;
#pragma unroll
            for (int nt = 0; nt < 8; nt++) {
                c[nt][e]   = __expf(c[nt][e]   - mnew);
                c[nt][e+1] = __expf(c[nt][e+1] - mnew);
                ps += c[nt][e] + c[nt][e+1];
            }
            ps += __shfl_xor_sync(0xffffffffu, ps, 1);
            ps += __shfl_xor_sync(0xffffffffu, ps, 2);
            lrow[r] = lrow[r] * alpha + ps;
            mrow[r] = mnew;
#pragma unroll
            for (int nt = 0; nt < 8; nt++) {
                oacc[nt][e]   *= alpha;
                oacc[nt][e+1] *= alpha;
            }
        }

        // ---- PV (fp16): single-P x single-V, 1 MMA per n-tile ----
#pragma unroll
        for (int ks = 0; ks < 4; ks++) {
            uint32_t ph[4];
            ph[0] = pack_h2(c[2*ks][0],   c[2*ks][1]);
            ph[1] = pack_h2(c[2*ks][2],   c[2*ks][3]);
            ph[2] = pack_h2(c[2*ks+1][0], c[2*ks+1][1]);
            ph[3] = pack_h2(c[2*ks+1][2], c[2*ks+1][3]);
#pragma unroll
            for (int np = 0; np < 4; np++) {
                int n = np * 16 + b_nofs;
                uint32_t vh[4];
                LDMATRIX_X4(vh[0], vh[1], vh[2], vh[3],
                            sbase + (uint32_t)(TV + n * 72 + ks * 16 + b_kofs) * 2);
                uint32_t b0h[2] = {vh[0], vh[1]}, b1h[2] = {vh[2], vh[3]};
                mma_f16(oacc[np*2],   ph, b0h);
                mma_f16(oacc[np*2+1], ph, b1h);
            }
        }
    }

    // ---- epilogue: out[b][s][h*64+dv] = oacc / (l * 8) ----
    const int b = bh >> 4, h = bh & 15;
#pragma unroll
    for (int half = 0; half < 2; half++) {
        int srow = qbase + wq * 16 + quad + half * 8;
        float inv = 1.0f / (lrow[half] * 8.0f);
        float* dst = out + ((size_t)(b * SEQ + srow)) * (NHEADS * DHEAD) + h * DHEAD;
#pragma unroll
        for (int nt = 0; nt < 8; nt++) {
            int col = nt * 8 + pr * 2;
            float2 v;
            v.x = oacc[nt][half*2 + 0] * inv;
            v.y = oacc[nt][half*2 + 1] * inv;
            *(float2*)(dst + col) = v;
        }
    }
}

// ---------------------------------------------------------------------------
extern "C" void kernel_launch(void* const* d_in, const int* in_sizes, int n_in,
                              void* d_out, int out_size)
{
    const float* x  = (const float*)d_in[0];
    const float* Wq = (const float*)d_in[1];
    const float* bq = (const float*)d_in[2];
    const float* Wk = (const float*)d_in[3];
    const float* bk = (const float*)d_in[4];
    const float* Wv = (const float*)d_in[5];
    const float* bv = (const float*)d_in[6];
    float* out = (float*)d_out;

    cudaFuncSetAttribute(proj_mma, cudaFuncAttributeMaxDynamicSharedMemorySize,
                         PROJ_SMEM_ELEMS * 2);
    cudaFuncSetAttribute(proj_v, cudaFuncAttributeMaxDynamicSharedMemorySize,
                         PROJV_SMEM);
    cudaFuncSetAttribute(attn_mma, cudaFuncAttributeMaxDynamicSharedMemorySize,
                         ATTN_SMEM_BYTES);

    convert_x<<<(NTOK * INDIM / 4) / 256, 256>>>(x);
    convert_w<<<dim3(INDIM / 64, NHEADS * 3), 256>>>(Wq, Wk, Wv);
    proj_mma<<<dim3(NTOK / 128, NHEADS, 2), 128, PROJ_SMEM_ELEMS * 2>>>(bq, bk);
    proj_v<<<dim3(NTOK / 128, NHEADS), 128, PROJV_SMEM>>>(bv);
    convert_vt<<<dim3(SEQ / 64, BH), 256>>>();
    attn_mma<<<dim3(SEQ / 64, BH), 128, ATTN_SMEM_BYTES>>>(out);
}